// round 8
// baseline (speedup 1.0000x reference)
#include <cuda_runtime.h>
#include <cuda_fp16.h>
#include <math.h>
#include <stdint.h>

#define Tn 1024
#define Hn 1024
#define En 64
#define In 512
#define TWO_I 1024
#define Gn 8
#define EPG 8
#define TOPKG 4
#define TOPK 8
#define NV 65                 // 64 routed + 1 shared (virtual expert 64)

#define BM 64
#define BK 32

// ---------------- device scratch ----------------
__device__ int    g_counts[NV];
__device__ int    g_offsets[NV];
__device__ int    g_tokens[NV * Tn];
__device__ int    g_tk_e[Tn * TOPK];
__device__ int    g_tk_pos[Tn * TOPK];
__device__ float  g_tk_w[Tn * TOPK];
__device__ __half g_xh[(size_t)Tn * Hn];                     // x fp16 [t][h]
__device__ __half g_wgu16[(size_t)NV * TWO_I * Hn];          // [e][n][h]  (transposed) 136MB
__device__ __half g_wd16[(size_t)NV * Hn * In];              // [e][h][i]  (transposed) 68MB
__device__ __half g_act16[(size_t)(Tn * TOPK + Tn) * In];    // fp16 act
__device__ float  g_down[(size_t)(Tn * TOPK + Tn) * Hn];

// ---------------- helpers ----------------
__device__ __forceinline__ void mma_f16(float* d, unsigned a0, unsigned a1,
                                        unsigned a2, unsigned a3,
                                        unsigned b0, unsigned b1) {
    asm volatile(
        "mma.sync.aligned.m16n8k16.row.col.f32.f16.f16.f32 "
        "{%0,%1,%2,%3}, {%4,%5,%6,%7}, {%8,%9}, {%0,%1,%2,%3};"
        : "+f"(d[0]), "+f"(d[1]), "+f"(d[2]), "+f"(d[3])
        : "r"(a0), "r"(a1), "r"(a2), "r"(a3), "r"(b0), "r"(b1));
}

__device__ __forceinline__ void cpa16(uint32_t dst, const void* src) {
    asm volatile("cp.async.cg.shared.global [%0], [%1], 16;" :: "r"(dst), "l"(src));
}
__device__ __forceinline__ void cpa_commit() { asm volatile("cp.async.commit_group;"); }
__device__ __forceinline__ void cpa_wait1()  { asm volatile("cp.async.wait_group 1;"); }
__device__ __forceinline__ void cpa_wait0()  { asm volatile("cp.async.wait_group 0;"); }

__device__ __forceinline__ uint32_t smem_u32(const void* p) {
    uint32_t a;
    asm("{ .reg .u64 t; cvta.to.shared.u64 t, %1; cvt.u32.u64 %0, t; }" : "=r"(a) : "l"(p));
    return a;
}

// smem geometry (in 32-bit words). Row stride 20 words = 40 halves = 80B.
// word-stride 20 mod 32 = 20 -> qr*20 spans {0,20,8,28,16,4,24,12}: conflict-free.
#define RSW   20
#define AWORDS (64 * RSW)     // 1280 words per A buffer
#define BWORDS (256 * RSW)    // 5120 words per B buffer
#define SMEM_BYTES ((2 * AWORDS + 2 * BWORDS) * 4)   // 51200

// ---------------- kernel 0: prep x -> fp16, init counts ----------------
__global__ void k_prep(const float* __restrict__ x) {
    if (blockIdx.x == 0) {
        if (threadIdx.x < En) g_counts[threadIdx.x] = 0;
        if (threadIdx.x == En) g_counts[En] = Tn;
    }
    int i = blockIdx.x * 256 + threadIdx.x;   // float4 index
    float4 v = ((const float4*)x)[i];
    __half2 p0 = __floats2half2_rn(v.x, v.y);
    __half2 p1 = __floats2half2_rn(v.z, v.w);
    ((__half2*)g_xh)[i * 2 + 0] = p0;
    ((__half2*)g_xh)[i * 2 + 1] = p1;
}

// ---------------- conversion: w_gate_up [h][n] -> fp16 [n][h] ----------------
__global__ void k_cvt_gu(const float* __restrict__ wgu,
                         const float* __restrict__ shgu) {
    const int e = blockIdx.z;
    const float* src = (e < En) ? (wgu + (size_t)e * Hn * TWO_I) : shgu;
    __half* dst = g_wgu16 + (size_t)e * TWO_I * Hn;
    __shared__ __half s[32][36];   // [n][h]
    const int tid = threadIdx.x;
    const int rl = tid >> 3, c4 = (tid & 7) * 4;
    {   // read: fixed h row, 4 consecutive n
        int h = blockIdx.y * 32 + rl;
        int n = blockIdx.x * 32 + c4;
        float4 v = *(const float4*)(src + (size_t)h * TWO_I + n);
        s[c4 + 0][rl] = __float2half_rn(v.x);
        s[c4 + 1][rl] = __float2half_rn(v.y);
        s[c4 + 2][rl] = __float2half_rn(v.z);
        s[c4 + 3][rl] = __float2half_rn(v.w);
    }
    __syncthreads();
    {   // write: fixed n row, 4 consecutive h
        int n = blockIdx.x * 32 + rl;
        int h = blockIdx.y * 32 + c4;
        __half2 p0 = __halves2half2(s[rl][c4 + 0], s[rl][c4 + 1]);
        __half2 p1 = __halves2half2(s[rl][c4 + 2], s[rl][c4 + 3]);
        __half2* d = (__half2*)(dst + (size_t)n * Hn + h);
        d[0] = p0; d[1] = p1;
    }
}

// ---------------- conversion: w_down [i][h] -> fp16 [h][i] ----------------
__global__ void k_cvt_d(const float* __restrict__ wd,
                        const float* __restrict__ shd) {
    const int e = blockIdx.z;
    const float* src = (e < En) ? (wd + (size_t)e * In * Hn) : shd;
    __half* dst = g_wd16 + (size_t)e * Hn * In;
    __shared__ __half s[32][36];   // [h][i]
    const int tid = threadIdx.x;
    const int rl = tid >> 3, c4 = (tid & 7) * 4;
    {   // read: fixed i row, 4 consecutive h
        int i = blockIdx.x * 32 + rl;
        int h = blockIdx.y * 32 + c4;
        float4 v = *(const float4*)(src + (size_t)i * Hn + h);
        s[c4 + 0][rl] = __float2half_rn(v.x);
        s[c4 + 1][rl] = __float2half_rn(v.y);
        s[c4 + 2][rl] = __float2half_rn(v.z);
        s[c4 + 3][rl] = __float2half_rn(v.w);
    }
    __syncthreads();
    {   // write: fixed h row, 4 consecutive i
        int h = blockIdx.y * 32 + rl;
        int i = blockIdx.x * 32 + c4;
        __half2 p0 = __halves2half2(s[rl][c4 + 0], s[rl][c4 + 1]);
        __half2 p1 = __halves2half2(s[rl][c4 + 2], s[rl][c4 + 3]);
        __half2* d = (__half2*)(dst + (size_t)h * In + i);
        d[0] = p0; d[1] = p1;
    }
}

// ---------------- kernel 1: routing (exact fp32) ----------------
__global__ void k_route(const float* __restrict__ x,
                        const float* __restrict__ gw,
                        const float* __restrict__ ebias) {
    int t = blockIdx.x;
    int tid = threadIdx.x;
    __shared__ float s_x[Hn];
    __shared__ float s_sc[En];
    __shared__ float s_ch[En];

    for (int i = tid; i < Hn / 4; i += 256)
        ((float4*)s_x)[i] = ((const float4*)(x + (size_t)t * Hn))[i];
    __syncthreads();

    int e = tid >> 2, p = tid & 3;
    const float* gr = gw + (size_t)e * Hn;
    float part = 0.f;
    #pragma unroll 8
    for (int j = 0; j < Hn / 4; j++) {
        int h = j * 4 + p;
        part += s_x[h] * gr[h];
    }
    part += __shfl_xor_sync(0xffffffffu, part, 1);
    part += __shfl_xor_sync(0xffffffffu, part, 2);
    if (p == 0) {
        float sc = 1.f / (1.f + expf(-part));
        s_sc[e] = sc;
        s_ch[e] = sc + ebias[e];
    }
    if (tid == 0) g_tokens[En * Tn + t] = t;
    __syncthreads();

    if (tid == 0) {
        float gs[Gn];
        #pragma unroll
        for (int g = 0; g < Gn; g++) {
            float m1 = -1e38f, m2 = -1e38f;
            #pragma unroll
            for (int j = 0; j < EPG; j++) {
                float v = s_ch[g * EPG + j];
                if (v > m1) { m2 = m1; m1 = v; }
                else if (v > m2) { m2 = v; }
            }
            gs[g] = m1 + m2;
        }
        unsigned gsel = 0;
        #pragma unroll
        for (int it = 0; it < TOPKG; it++) {
            float best = -1e38f; int bi = 0;
            #pragma unroll
            for (int g = 0; g < Gn; g++)
                if (!((gsel >> g) & 1u) && gs[g] > best) { best = gs[g]; bi = g; }
            gsel |= 1u << bi;
        }
        unsigned long long taken = 0ull;
        int eidx[TOPK]; float ws[TOPK]; float wsum = 0.f;
        #pragma unroll
        for (int it = 0; it < TOPK; it++) {
            float best = -1e38f; int bi = 0;
            for (int ee = 0; ee < En; ee++) {
                if (((gsel >> (ee >> 3)) & 1u) && !((taken >> ee) & 1ull)) {
                    float v = s_ch[ee];
                    if (v > best) { best = v; bi = ee; }
                }
            }
            taken |= 1ull << bi;
            eidx[it] = bi; ws[it] = s_sc[bi]; wsum += s_sc[bi];
        }
        float scale = 1.0f / wsum;
        #pragma unroll
        for (int k = 0; k < TOPK; k++) {
            int ee = eidx[k];
            int pos = atomicAdd(&g_counts[ee], 1);
            g_tokens[ee * Tn + pos] = t;
            g_tk_e[t * TOPK + k]   = ee;
            g_tk_pos[t * TOPK + k] = pos;
            g_tk_w[t * TOPK + k]   = ws[k] * scale;
        }
    }
}

// ---------------- kernel 2: offsets ----------------
__global__ void k_scan() {
    __shared__ int s[NV];
    int tid = threadIdx.x;
    if (tid < NV) s[tid] = g_counts[tid];
    __syncthreads();
    if (tid == 0) {
        int off = 0;
        for (int e = 0; e < NV; e++) { g_offsets[e] = off; off += s[e]; }
    }
}

// ---------------- kernel 3: gate_up GEMM (fp16) + SiLU*up ----------------
// Block 64M x (128 gate + 128 up), BK=32, 128 threads, 4 warps (n-split).
// Warp 64M x 32N dual. B tile rows 0-127 gate, 128-255 up (K-contiguous fp16).
__global__ __launch_bounds__(128, 2) void k_gemm1() {
    const int e = blockIdx.y;
    const int n_e = g_counts[e];
    const int nb = blockIdx.x & 3;
    const int mt = blockIdx.x >> 2;
    const int row0 = mt * BM;
    if (row0 >= n_e) return;
    const __half* Bp = g_wgu16 + (size_t)e * TWO_I * Hn;
    const int off_e = g_offsets[e];
    const int colg = nb * 128;

    extern __shared__ uint32_t smw[];
    const uint32_t sb = smem_u32(smw);
    const int tid = threadIdx.x;

    // A: 2 chunks16/thread: id = tid + 128l: row=id>>2, c16=id&3
    const __half* a_src[2];
    uint32_t a_dst[2];
    #pragma unroll
    for (int l = 0; l < 2; l++) {
        int id = tid + 128 * l;
        int row = id >> 2, c16 = id & 3;
        int ridx = row0 + row; if (ridx > n_e - 1) ridx = n_e - 1;
        a_src[l] = g_xh + (size_t)g_tokens[e * Tn + ridx] * Hn + c16 * 8;
        a_dst[l] = sb + (row * RSW + c16 * 4) * 4;
    }
    // B: 8 chunks16/thread
    const __half* b_src[8];
    uint32_t b_dst[8];
    #pragma unroll
    for (int l = 0; l < 8; l++) {
        int id = tid + 128 * l;
        int row = id >> 2, c16 = id & 3;
        int n = colg + row + ((row < 128) ? 0 : (In - 128));
        b_src[l] = Bp + (size_t)n * Hn + c16 * 8;
        b_dst[l] = sb + (2 * AWORDS + row * RSW + c16 * 4) * 4;
    }

    const int wn = tid >> 5, lane = tid & 31;
    const int qr = lane >> 2, qc = lane & 3;

    float accG[4][4][4], accU[4][4][4];
    #pragma unroll
    for (int m = 0; m < 4; m++)
        #pragma unroll
        for (int n = 0; n < 4; n++)
            #pragma unroll
            for (int j = 0; j < 4; j++) { accG[m][n][j] = 0.f; accU[m][n][j] = 0.f; }

    #pragma unroll
    for (int l = 0; l < 2; l++) cpa16(a_dst[l], a_src[l]);
    #pragma unroll
    for (int l = 0; l < 8; l++) cpa16(b_dst[l], b_src[l]);
    cpa_commit();

    const int KT = Hn / BK;  // 32
    for (int kt = 0; kt < KT; kt++) {
        int buf = kt & 1;
        if (kt + 1 < KT) {
            int nbuf = buf ^ 1;
            uint32_t aoff = nbuf ? AWORDS * 4 : 0;
            uint32_t boff = nbuf ? BWORDS * 4 : 0;
            size_t ka = (size_t)(kt + 1) * BK;
            #pragma unroll
            for (int l = 0; l < 2; l++) cpa16(a_dst[l] + aoff, a_src[l] + ka);
            #pragma unroll
            for (int l = 0; l < 8; l++) cpa16(b_dst[l] + boff, b_src[l] + ka);
            cpa_commit();
            cpa_wait1();
        } else {
            cpa_wait0();
        }
        __syncthreads();

        const uint32_t* Ab = smw + buf * AWORDS;
        const uint32_t* Bb = smw + 2 * AWORDS + buf * BWORDS;
        #pragma unroll
        for (int ks2 = 0; ks2 < 2; ks2++) {
            const int ksw = ks2 * 8 + qc;
            uint32_t a[4][4];
            #pragma unroll
            for (int m = 0; m < 4; m++) {
                int r0 = m * 16 + qr;
                a[m][0] = Ab[r0 * RSW + ksw];
                a[m][1] = Ab[(r0 + 8) * RSW + ksw];
                a[m][2] = Ab[r0 * RSW + ksw + 4];
                a[m][3] = Ab[(r0 + 8) * RSW + ksw + 4];
            }
            #pragma unroll
            for (int n = 0; n < 4; n++) {
                int cg = wn * 32 + n * 8 + qr;
                uint32_t bg0 = Bb[cg * RSW + ksw];
                uint32_t bg1 = Bb[cg * RSW + ksw + 4];
                #pragma unroll
                for (int m = 0; m < 4; m++)
                    mma_f16(accG[m][n], a[m][0], a[m][1], a[m][2], a[m][3], bg0, bg1);
                int cu = cg + 128;
                uint32_t bu0 = Bb[cu * RSW + ksw];
                uint32_t bu1 = Bb[cu * RSW + ksw + 4];
                #pragma unroll
                for (int m = 0; m < 4; m++)
                    mma_f16(accU[m][n], a[m][0], a[m][1], a[m][2], a[m][3], bu0, bu1);
            }
        }
        __syncthreads();
    }

    // epilogue: silu(g)*u -> fp16
    #pragma unroll
    for (int m = 0; m < 4; m++) {
        #pragma unroll
        for (int n = 0; n < 4; n++) {
            #pragma unroll
            for (int half_ = 0; half_ < 2; half_++) {
                int r = m * 16 + qr + half_ * 8;
                int grow = row0 + r;
                if (grow < n_e) {
                    int c = colg + wn * 32 + n * 8 + qc * 2;
                    float gv0 = accG[m][n][half_ * 2 + 0];
                    float uv0 = accU[m][n][half_ * 2 + 0];
                    float gv1 = accG[m][n][half_ * 2 + 1];
                    float uv1 = accU[m][n][half_ * 2 + 1];
                    float o0 = gv0 / (1.f + expf(-gv0)) * uv0;
                    float o1 = gv1 / (1.f + expf(-gv1)) * uv1;
                    *(__half2*)(g_act16 + (size_t)(off_e + grow) * In + c) =
                        __floats2half2_rn(o0, o1);
                }
            }
        }
    }
}

// ---------------- kernel 4: down GEMM (fp16) ----------------
// Block 64M x 256N, 4 warps n-split, warp 64M x 64N.
__global__ __launch_bounds__(128, 2) void k_gemm2() {
    const int e = blockIdx.y;
    const int n_e = g_counts[e];
    const int nb = blockIdx.x & 3;
    const int mt = blockIdx.x >> 2;
    const int row0 = mt * BM;
    if (row0 >= n_e) return;
    const __half* Bp = g_wd16 + (size_t)e * Hn * In;
    const int off_e = g_offsets[e];
    const int colb = nb * 256;

    extern __shared__ uint32_t smw[];
    const uint32_t sb = smem_u32(smw);
    const int tid = threadIdx.x;

    const __half* a_src[2];
    uint32_t a_dst[2];
    #pragma unroll
    for (int l = 0; l < 2; l++) {
        int id = tid + 128 * l;
        int row = id >> 2, c16 = id & 3;
        int ridx = row0 + row; if (ridx > n_e - 1) ridx = n_e - 1;
        a_src[l] = g_act16 + (size_t)(off_e + ridx) * In + c16 * 8;
        a_dst[l] = sb + (row * RSW + c16 * 4) * 4;
    }
    const __half* b_src[8];
    uint32_t b_dst[8];
    #pragma unroll
    for (int l = 0; l < 8; l++) {
        int id = tid + 128 * l;
        int row = id >> 2, c16 = id & 3;
        b_src[l] = Bp + (size_t)(colb + row) * In + c16 * 8;
        b_dst[l] = sb + (2 * AWORDS + row * RSW + c16 * 4) * 4;
    }

    const int wn = tid >> 5, lane = tid & 31;
    const int qr = lane >> 2, qc = lane & 3;

    float acc[4][8][4];
    #pragma unroll
    for (int m = 0; m < 4; m++)
        #pragma unroll
        for (int n = 0; n < 8; n++)
            #pragma unroll
            for (int j = 0; j < 4; j++) acc[m][n][j] = 0.f;

    #pragma unroll
    for (int l = 0; l < 2; l++) cpa16(a_dst[l], a_src[l]);
    #pragma unroll
    for (int l = 0; l < 8; l++) cpa16(b_dst[l], b_src[l]);
    cpa_commit();

    const int KT = In / BK;  // 16
    for (int kt = 0; kt < KT; kt++) {
        int buf = kt & 1;
        if (kt + 1 < KT) {
            int nbuf = buf ^ 1;
            uint32_t aoff = nbuf ? AWORDS * 4 : 0;
            uint32_t boff = nbuf ? BWORDS * 4 : 0;
            size_t ka = (size_t)(kt + 1) * BK;
            #pragma unroll
            for (int l = 0; l < 2; l++) cpa16(a_dst[l] + aoff, a_src[l] + ka);
            #pragma unroll
            for (int l = 0; l < 8; l++) cpa16(b_dst[l] + boff, b_src[l] + ka);
            cpa_commit();
            cpa_wait1();
        } else {
            cpa_wait0();
        }
        __syncthreads();

        const uint32_t* Ab = smw + buf * AWORDS;
        const uint32_t* Bb = smw + 2 * AWORDS + buf * BWORDS;
        #pragma unroll
        for (int ks2 = 0; ks2 < 2; ks2++) {
            const int ksw = ks2 * 8 + qc;
            uint32_t a[4][4];
            #pragma unroll
            for (int m = 0; m < 4; m++) {
                int r0 = m * 16 + qr;
                a[m][0] = Ab[r0 * RSW + ksw];
                a[m][1] = Ab[(r0 + 8) * RSW + ksw];
                a[m][2] = Ab[r0 * RSW + ksw + 4];
                a[m][3] = Ab[(r0 + 8) * RSW + ksw + 4];
            }
            #pragma unroll
            for (int n = 0; n < 8; n++) {
                int c = wn * 64 + n * 8 + qr;
                uint32_t b0 = Bb[c * RSW + ksw];
                uint32_t b1 = Bb[c * RSW + ksw + 4];
                #pragma unroll
                for (int m = 0; m < 4; m++)
                    mma_f16(acc[m][n], a[m][0], a[m][1], a[m][2], a[m][3], b0, b1);
            }
        }
        __syncthreads();
    }

    #pragma unroll
    for (int m = 0; m < 4; m++) {
        #pragma unroll
        for (int n = 0; n < 8; n++) {
            #pragma unroll
            for (int half_ = 0; half_ < 2; half_++) {
                int r = m * 16 + qr + half_ * 8;
                int grow = row0 + r;
                if (grow < n_e) {
                    int c = colb + wn * 64 + n * 8 + qc * 2;
                    float2 o;
                    o.x = acc[m][n][half_ * 2 + 0];
                    o.y = acc[m][n][half_ * 2 + 1];
                    *(float2*)(g_down + (size_t)(off_e + grow) * Hn + c) = o;
                }
            }
        }
    }
}

// ---------------- kernel 5: weighted combine ----------------
__global__ void k_combine(float* __restrict__ out) {
    int t = blockIdx.x, tid = threadIdx.x;
    __shared__ int s_slot[9];
    __shared__ float s_w[9];
    if (tid < TOPK) {
        int ee = g_tk_e[t * TOPK + tid];
        s_slot[tid] = g_offsets[ee] + g_tk_pos[t * TOPK + tid];
        s_w[tid] = g_tk_w[t * TOPK + tid];
    } else if (tid == TOPK) {
        s_slot[8] = g_offsets[En] + t;
        s_w[8] = 1.f;
    }
    __syncthreads();
    int h = tid * 4;
    float4 acc = make_float4(0.f, 0.f, 0.f, 0.f);
    #pragma unroll
    for (int j = 0; j < 9; j++) {
        float4 v = *(const float4*)(g_down + (size_t)s_slot[j] * Hn + h);
        float wv = s_w[j];
        acc.x += wv * v.x; acc.y += wv * v.y;
        acc.z += wv * v.z; acc.w += wv * v.w;
    }
    *(float4*)(out + (size_t)t * Hn + h) = acc;
}

// ---------------- launch ----------------
extern "C" void kernel_launch(void* const* d_in, const int* in_sizes, int n_in,
                              void* d_out, int out_size) {
    const float* x    = (const float*)d_in[0];
    const float* gw   = (const float*)d_in[1];
    const float* eb   = (const float*)d_in[2];
    const float* wgu  = (const float*)d_in[3];
    const float* wd   = (const float*)d_in[4];
    const float* shgu = (const float*)d_in[5];
    const float* shd  = (const float*)d_in[6];
    float* out = (float*)d_out;

    cudaFuncSetAttribute(k_gemm1, cudaFuncAttributeMaxDynamicSharedMemorySize, SMEM_BYTES);
    cudaFuncSetAttribute(k_gemm2, cudaFuncAttributeMaxDynamicSharedMemorySize, SMEM_BYTES);

    k_prep<<<Tn * Hn / 4 / 256, 256>>>(x);
    k_cvt_gu<<<dim3(TWO_I / 32, Hn / 32, NV), 256>>>(wgu, shgu);
    k_cvt_d<<<dim3(In / 32, Hn / 32, NV), 256>>>(wd, shd);
    k_route<<<Tn, 256>>>(x, gw, eb);
    k_scan<<<1, 128>>>();
    k_gemm1<<<dim3(16 * 4, NV), 128, SMEM_BYTES>>>();
    k_gemm2<<<dim3(16 * 4, NV), 128, SMEM_BYTES>>>();
    k_combine<<<Tn, 256>>>(out);
}

// round 9
// speedup vs baseline: 1.4180x; 1.4180x over previous
#include <cuda_runtime.h>
#include <math.h>

#define Tn 1024
#define Hn 1024
#define En 64
#define In 512
#define TWO_I 1024
#define Gn 8
#define EPG 8
#define TOPKG 4
#define TOPK 8
#define NV 65                 // 64 routed + 1 shared (virtual expert 64)

#define BM 64
#define BK 32

// bias correction for tf32 truncation (round-to-zero) of B operands
#define CF 1.00034f

// ---------------- device scratch ----------------
__device__ int   g_counts[NV];
__device__ int   g_offsets[NV];
__device__ int   g_tokens[NV * Tn];
__device__ int   g_tk_e[Tn * TOPK];
__device__ int   g_tk_pos[Tn * TOPK];
__device__ float g_tk_w[Tn * TOPK];
__device__ float g_sc[Tn * En];
__device__ float g_ch[Tn * En];
__device__ float g_xr[(size_t)Tn * Hn];                  // x pre-rounded to tf32
__device__ float g_act[(size_t)(Tn * TOPK + Tn) * In];   // tf32 values
__device__ float g_down[(size_t)(Tn * TOPK + Tn) * Hn];

// ---------------- helpers ----------------
__device__ __forceinline__ unsigned f2tf(float f) {
    unsigned u;
    asm("cvt.rna.tf32.f32 %0, %1;" : "=r"(u) : "f"(f));
    return u;
}

__device__ __forceinline__ void mma_tf32(float* d, unsigned a0, unsigned a1,
                                         unsigned a2, unsigned a3,
                                         unsigned b0, unsigned b1) {
    asm volatile(
        "mma.sync.aligned.m16n8k8.row.col.f32.tf32.tf32.f32 "
        "{%0,%1,%2,%3}, {%4,%5,%6,%7}, {%8,%9}, {%0,%1,%2,%3};"
        : "+f"(d[0]), "+f"(d[1]), "+f"(d[2]), "+f"(d[3])
        : "r"(a0), "r"(a1), "r"(a2), "r"(a3), "r"(b0), "r"(b1));
}

__device__ __forceinline__ void cpa16(void* dst, const void* src) {
    unsigned d = (unsigned)__cvta_generic_to_shared(dst);
    asm volatile("cp.async.cg.shared.global [%0], [%1], 16;" :: "r"(d), "l"(src));
}
__device__ __forceinline__ void cpa_commit() { asm volatile("cp.async.commit_group;"); }
__device__ __forceinline__ void cpa_wait1()  { asm volatile("cp.async.wait_group 1;"); }
__device__ __forceinline__ void cpa_wait0()  { asm volatile("cp.async.wait_group 0;"); }

#define AS_P 36    // mod32==4: A frag conflict-free
#define BGP  136   // mod32==8: B frag conflict-free
#define BSP2 264   // mod32==8

// ---------------- kernel 0: prep (tf32 pre-round of x) + init ----------------
__global__ void k_prep(const float* __restrict__ x) {
    if (blockIdx.x == 0) {
        if (threadIdx.x < En) g_counts[threadIdx.x] = 0;
        if (threadIdx.x == En) g_counts[En] = Tn;
    }
    int i = blockIdx.x * 256 + threadIdx.x;
    float4 v = ((const float4*)x)[i];
    v.x = __uint_as_float(f2tf(v.x));
    v.y = __uint_as_float(f2tf(v.y));
    v.z = __uint_as_float(f2tf(v.z));
    v.w = __uint_as_float(f2tf(v.w));
    ((float4*)g_xr)[i] = v;
}

// ---------------- kernel 1a: routing logits (fp32 tiled GEMM) ----------------
// 8 tokens/block, 256 threads = 64 experts x 4 quarters. Quarter p owns
// float4 columns {p + 4k}. gate_w row read once per block (8-way token reuse).
__global__ __launch_bounds__(256) void k_logits(const float* __restrict__ x,
                                                const float* __restrict__ gw,
                                                const float* __restrict__ eb) {
    __shared__ float4 sx[8][256];   // 8 tokens x 1024 floats = 32 KB
    const int t0 = blockIdx.x * 8;
    const int tid = threadIdx.x;

    #pragma unroll
    for (int l = 0; l < 8; l++) {
        int idx = tid + l * 256;
        int tok = idx >> 8, c = idx & 255;
        sx[tok][c] = ((const float4*)(x + (size_t)(t0 + tok) * Hn))[c];
    }
    __syncthreads();

    const int e = tid >> 2, p = tid & 3;
    const float4* gr = (const float4*)(gw + (size_t)e * Hn);
    float acc[8];
    #pragma unroll
    for (int tok = 0; tok < 8; tok++) acc[tok] = 0.f;

    #pragma unroll 4
    for (int k = 0; k < 64; k++) {
        float4 g = gr[p + 4 * k];
        #pragma unroll
        for (int tok = 0; tok < 8; tok++) {
            float4 xv = sx[tok][p + 4 * k];
            acc[tok] += g.x * xv.x + g.y * xv.y + g.z * xv.z + g.w * xv.w;
        }
    }
    #pragma unroll
    for (int tok = 0; tok < 8; tok++) {
        acc[tok] += __shfl_xor_sync(0xffffffffu, acc[tok], 1);
        acc[tok] += __shfl_xor_sync(0xffffffffu, acc[tok], 2);
    }
    if (p == 0) {
        float b = eb[e];
        #pragma unroll
        for (int tok = 0; tok < 8; tok++) {
            float sc = 1.f / (1.f + expf(-acc[tok]));
            g_sc[(t0 + tok) * En + e] = sc;
            g_ch[(t0 + tok) * En + e] = sc + b;
        }
    }
}

// ---------------- kernel 1b: grouped top-k selection ----------------
// 1 warp per token; scores staged in smem; lane 0 runs exact fp32 selection
// (identical semantics to the reference: strict '>' => lowest index on ties).
__global__ __launch_bounds__(256) void k_topk() {
    __shared__ float s_sc[8][En];
    __shared__ float s_ch[8][En];
    const int w = threadIdx.x >> 5, lane = threadIdx.x & 31;
    const int t = blockIdx.x * 8 + w;

    s_sc[w][lane]      = g_sc[t * En + lane];
    s_sc[w][lane + 32] = g_sc[t * En + lane + 32];
    s_ch[w][lane]      = g_ch[t * En + lane];
    s_ch[w][lane + 32] = g_ch[t * En + lane + 32];
    __syncwarp();

    if (lane == 0) {
        g_tokens[En * Tn + t] = t;   // shared-expert token list
        float gs[Gn];
        #pragma unroll
        for (int g = 0; g < Gn; g++) {
            float m1 = -1e38f, m2 = -1e38f;
            #pragma unroll
            for (int j = 0; j < EPG; j++) {
                float v = s_ch[w][g * EPG + j];
                if (v > m1) { m2 = m1; m1 = v; }
                else if (v > m2) { m2 = v; }
            }
            gs[g] = m1 + m2;
        }
        unsigned gsel = 0;
        #pragma unroll
        for (int it = 0; it < TOPKG; it++) {
            float best = -1e38f; int bi = 0;
            #pragma unroll
            for (int g = 0; g < Gn; g++)
                if (!((gsel >> g) & 1u) && gs[g] > best) { best = gs[g]; bi = g; }
            gsel |= 1u << bi;
        }
        unsigned long long taken = 0ull;
        int eidx[TOPK]; float ws[TOPK]; float wsum = 0.f;
        #pragma unroll
        for (int it = 0; it < TOPK; it++) {
            float best = -1e38f; int bi = 0;
            for (int ee = 0; ee < En; ee++) {
                if (((gsel >> (ee >> 3)) & 1u) && !((taken >> ee) & 1ull)) {
                    float v = s_ch[w][ee];
                    if (v > best) { best = v; bi = ee; }
                }
            }
            taken |= 1ull << bi;
            eidx[it] = bi; ws[it] = s_sc[w][bi]; wsum += s_sc[w][bi];
        }
        float scale = 1.0f / wsum;
        #pragma unroll
        for (int k = 0; k < TOPK; k++) {
            int ee = eidx[k];
            int pos = atomicAdd(&g_counts[ee], 1);
            g_tokens[ee * Tn + pos] = t;
            g_tk_e[t * TOPK + k]   = ee;
            g_tk_pos[t * TOPK + k] = pos;
            g_tk_w[t * TOPK + k]   = ws[k] * scale;
        }
    }
}

// ---------------- kernel 2: offsets ----------------
__global__ void k_scan() {
    __shared__ int s[NV];
    int tid = threadIdx.x;
    if (tid < NV) s[tid] = g_counts[tid];
    __syncthreads();
    if (tid == 0) {
        int off = 0;
        for (int e = 0; e < NV; e++) { g_offsets[e] = off; off += s[e]; }
    }
}

// ---------------- kernel 3: gate_up GEMM + SiLU*up (tf32 raw-bit) ----------------
// 128 threads, 4 warps in n. Block 64M x (128 gate + 128 up).
// Warp tile: 64M x 32N dual (gate+up).
__global__ __launch_bounds__(128, 2) void k_gemm1(const float* __restrict__ wgu,
                                                  const float* __restrict__ shgu) {
    const int e = blockIdx.y;
    const int n_e = g_counts[e];
    const int nb = blockIdx.x & 3;
    const int mt = blockIdx.x >> 2;
    const int row0 = mt * BM;
    if (row0 >= n_e) return;
    const float* Bp = (e < En) ? (wgu + (size_t)e * Hn * TWO_I) : shgu;
    const int off_e = g_offsets[e];
    const int colg = nb * 128;

    extern __shared__ float smem[];
    float* As = smem;                    // [2][64][AS_P]
    float* Bg = smem + 2 * BM * AS_P;    // [2][32][BGP]
    float* Bu = Bg + 2 * BK * BGP;       // [2][32][BGP]

    const int tid = threadIdx.x;

    const int ar = tid >> 3, ac = (tid & 7) * 4;
    const float* a_src[4];
    float* a_dst[4];
    #pragma unroll
    for (int l = 0; l < 4; l++) {
        int r = l * 16 + ar;
        int ridx = row0 + r; if (ridx > n_e - 1) ridx = n_e - 1;
        a_src[l] = g_xr + (size_t)g_tokens[e * Tn + ridx] * Hn + ac;
        a_dst[l] = As + r * AS_P + ac;
    }
    const int br = tid >> 5, bc = (tid & 31) * 4;
    const float* bgs = Bp + (size_t)br * TWO_I + colg + bc;
    const float* bus = bgs + In;
    float* bgd = Bg + br * BGP + bc;
    float* bud = Bu + br * BGP + bc;

    const int wn = tid >> 5, lane = tid & 31;
    const int qr = lane >> 2, qc = lane & 3;
    const int abuf = BM * AS_P, bbuf = BK * BGP;

    float accG[4][4][4], accU[4][4][4];
    #pragma unroll
    for (int m = 0; m < 4; m++)
        #pragma unroll
        for (int n = 0; n < 4; n++)
            #pragma unroll
            for (int j = 0; j < 4; j++) { accG[m][n][j] = 0.f; accU[m][n][j] = 0.f; }

    #pragma unroll
    for (int l = 0; l < 4; l++) cpa16(a_dst[l], a_src[l]);
    #pragma unroll
    for (int l = 0; l < 8; l++) {
        cpa16(bgd + l * 4 * BGP, bgs + (size_t)l * 4 * TWO_I);
        cpa16(bud + l * 4 * BGP, bus + (size_t)l * 4 * TWO_I);
    }
    cpa_commit();

    const int KT = Hn / BK;  // 32
    for (int kt = 0; kt < KT; kt++) {
        int buf = kt & 1;
        if (kt + 1 < KT) {
            int aoff = (buf ^ 1) ? abuf : 0;
            int boff = (buf ^ 1) ? bbuf : 0;
            size_t ka = (size_t)(kt + 1) * BK;
            #pragma unroll
            for (int l = 0; l < 4; l++) cpa16(a_dst[l] + aoff, a_src[l] + ka);
            #pragma unroll
            for (int l = 0; l < 8; l++) {
                cpa16(bgd + boff + l * 4 * BGP, bgs + ka * TWO_I + (size_t)l * 4 * TWO_I);
                cpa16(bud + boff + l * 4 * BGP, bus + ka * TWO_I + (size_t)l * 4 * TWO_I);
            }
            cpa_commit();
            cpa_wait1();
        } else {
            cpa_wait0();
        }
        __syncthreads();

        const float* Ab = As + buf * abuf;
        const float* Bgb = Bg + buf * bbuf;
        const float* Bub = Bu + buf * bbuf;
        #pragma unroll
        for (int ks = 0; ks < BK; ks += 8) {
            unsigned a[4][4];
            #pragma unroll
            for (int m = 0; m < 4; m++) {
                int r0 = m * 16 + qr;
                a[m][0] = __float_as_uint(Ab[r0 * AS_P + ks + qc]);
                a[m][1] = __float_as_uint(Ab[(r0 + 8) * AS_P + ks + qc]);
                a[m][2] = __float_as_uint(Ab[r0 * AS_P + ks + qc + 4]);
                a[m][3] = __float_as_uint(Ab[(r0 + 8) * AS_P + ks + qc + 4]);
            }
            #pragma unroll
            for (int n = 0; n < 4; n++) {
                int c = wn * 32 + n * 8 + qr;
                unsigned bg0 = __float_as_uint(Bgb[(ks + qc) * BGP + c]);
                unsigned bg1 = __float_as_uint(Bgb[(ks + qc + 4) * BGP + c]);
                #pragma unroll
                for (int m = 0; m < 4; m++)
                    mma_tf32(accG[m][n], a[m][0], a[m][1], a[m][2], a[m][3], bg0, bg1);
                unsigned bu0 = __float_as_uint(Bub[(ks + qc) * BGP + c]);
                unsigned bu1 = __float_as_uint(Bub[(ks + qc + 4) * BGP + c]);
                #pragma unroll
                for (int m = 0; m < 4; m++)
                    mma_tf32(accU[m][n], a[m][0], a[m][1], a[m][2], a[m][3], bu0, bu1);
            }
        }
        __syncthreads();
    }

    #pragma unroll
    for (int m = 0; m < 4; m++) {
        #pragma unroll
        for (int n = 0; n < 4; n++) {
            #pragma unroll
            for (int half_ = 0; half_ < 2; half_++) {
                int r = m * 16 + qr + half_ * 8;
                int grow = row0 + r;
                if (grow < n_e) {
                    int c = colg + wn * 32 + n * 8 + qc * 2;
                    float gv0 = accG[m][n][half_ * 2 + 0] * CF;
                    float uv0 = accU[m][n][half_ * 2 + 0] * CF;
                    float gv1 = accG[m][n][half_ * 2 + 1] * CF;
                    float uv1 = accU[m][n][half_ * 2 + 1] * CF;
                    float o0 = gv0 / (1.f + expf(-gv0)) * uv0;
                    float o1 = gv1 / (1.f + expf(-gv1)) * uv1;
                    float2 o;
                    o.x = __uint_as_float(f2tf(o0));
                    o.y = __uint_as_float(f2tf(o1));
                    *(float2*)(g_act + (size_t)(off_e + grow) * In + c) = o;
                }
            }
        }
    }
}

// ---------------- kernel 4: down GEMM (tf32 raw-bit) ----------------
__global__ __launch_bounds__(128, 2) void k_gemm2(const float* __restrict__ wd,
                                                  const float* __restrict__ shd) {
    const int e = blockIdx.y;
    const int n_e = g_counts[e];
    const int nb = blockIdx.x & 3;
    const int mt = blockIdx.x >> 2;
    const int row0 = mt * BM;
    if (row0 >= n_e) return;
    const float* Bp = (e < En) ? (wd + (size_t)e * In * Hn) : shd;
    const int off_e = g_offsets[e];
    const int colb = nb * 256;

    extern __shared__ float smem[];
    float* As = smem;                    // [2][64][AS_P]
    float* Bs = smem + 2 * BM * AS_P;    // [2][32][BSP2]

    const int tid = threadIdx.x;

    const int ar = tid >> 3, ac = (tid & 7) * 4;
    const float* a_src[4];
    float* a_dst[4];
    #pragma unroll
    for (int l = 0; l < 4; l++) {
        int r = l * 16 + ar;
        int ridx = row0 + r; if (ridx > n_e - 1) ridx = n_e - 1;
        a_src[l] = g_act + (size_t)(off_e + ridx) * In + ac;
        a_dst[l] = As + r * AS_P + ac;
    }
    const int br = tid >> 6, bc = (tid & 63) * 4;
    const float* bss = Bp + (size_t)br * Hn + colb + bc;
    float* bsd = Bs + br * BSP2 + bc;

    const int wn = tid >> 5, lane = tid & 31;
    const int qr = lane >> 2, qc = lane & 3;
    const int abuf = BM * AS_P, bbuf = BK * BSP2;

    float acc[4][8][4];
    #pragma unroll
    for (int m = 0; m < 4; m++)
        #pragma unroll
        for (int n = 0; n < 8; n++)
            #pragma unroll
            for (int j = 0; j < 4; j++) acc[m][n][j] = 0.f;

    #pragma unroll
    for (int l = 0; l < 4; l++) cpa16(a_dst[l], a_src[l]);
    #pragma unroll
    for (int l = 0; l < 16; l++)
        cpa16(bsd + l * 2 * BSP2, bss + (size_t)l * 2 * Hn);
    cpa_commit();

    const int KT = In / BK;  // 16
    for (int kt = 0; kt < KT; kt++) {
        int buf = kt & 1;
        if (kt + 1 < KT) {
            int aoff = (buf ^ 1) ? abuf : 0;
            int boff = (buf ^ 1) ? bbuf : 0;
            size_t ka = (size_t)(kt + 1) * BK;
            #pragma unroll
            for (int l = 0; l < 4; l++) cpa16(a_dst[l] + aoff, a_src[l] + ka);
            #pragma unroll
            for (int l = 0; l < 16; l++)
                cpa16(bsd + boff + l * 2 * BSP2, bss + ka * Hn + (size_t)l * 2 * Hn);
            cpa_commit();
            cpa_wait1();
        } else {
            cpa_wait0();
        }
        __syncthreads();

        const float* Ab = As + buf * abuf;
        const float* Bb = Bs + buf * bbuf;
        #pragma unroll
        for (int ks = 0; ks < BK; ks += 8) {
            unsigned a[4][4];
            #pragma unroll
            for (int m = 0; m < 4; m++) {
                int r0 = m * 16 + qr;
                a[m][0] = __float_as_uint(Ab[r0 * AS_P + ks + qc]);
                a[m][1] = __float_as_uint(Ab[(r0 + 8) * AS_P + ks + qc]);
                a[m][2] = __float_as_uint(Ab[r0 * AS_P + ks + qc + 4]);
                a[m][3] = __float_as_uint(Ab[(r0 + 8) * AS_P + ks + qc + 4]);
            }
            #pragma unroll
            for (int n = 0; n < 8; n++) {
                int c = wn * 64 + n * 8 + qr;
                unsigned b0 = __float_as_uint(Bb[(ks + qc) * BSP2 + c]);
                unsigned b1 = __float_as_uint(Bb[(ks + qc + 4) * BSP2 + c]);
                #pragma unroll
                for (int m = 0; m < 4; m++)
                    mma_tf32(acc[m][n], a[m][0], a[m][1], a[m][2], a[m][3], b0, b1);
            }
        }
        __syncthreads();
    }

    #pragma unroll
    for (int m = 0; m < 4; m++) {
        #pragma unroll
        for (int n = 0; n < 8; n++) {
            #pragma unroll
            for (int half_ = 0; half_ < 2; half_++) {
                int r = m * 16 + qr + half_ * 8;
                int grow = row0 + r;
                if (grow < n_e) {
                    int c = colb + wn * 64 + n * 8 + qc * 2;
                    float2 o;
                    o.x = acc[m][n][half_ * 2 + 0] * CF;
                    o.y = acc[m][n][half_ * 2 + 1] * CF;
                    *(float2*)(g_down + (size_t)(off_e + grow) * Hn + c) = o;
                }
            }
        }
    }
}

// ---------------- kernel 5: weighted combine ----------------
__global__ void k_combine(float* __restrict__ out) {
    int t = blockIdx.x, tid = threadIdx.x;
    __shared__ int s_slot[9];
    __shared__ float s_w[9];
    if (tid < TOPK) {
        int ee = g_tk_e[t * TOPK + tid];
        s_slot[tid] = g_offsets[ee] + g_tk_pos[t * TOPK + tid];
        s_w[tid] = g_tk_w[t * TOPK + tid];
    } else if (tid == TOPK) {
        s_slot[8] = g_offsets[En] + t;
        s_w[8] = 1.f;
    }
    __syncthreads();
    int h = tid * 4;
    float4 acc = make_float4(0.f, 0.f, 0.f, 0.f);
    #pragma unroll
    for (int j = 0; j < 9; j++) {
        float4 v = *(const float4*)(g_down + (size_t)s_slot[j] * Hn + h);
        float wv = s_w[j];
        acc.x += wv * v.x; acc.y += wv * v.y;
        acc.z += wv * v.z; acc.w += wv * v.w;
    }
    *(float4*)(out + (size_t)t * Hn + h) = acc;
}

// ---------------- launch ----------------
extern "C" void kernel_launch(void* const* d_in, const int* in_sizes, int n_in,
                              void* d_out, int out_size) {
    const float* x    = (const float*)d_in[0];
    const float* gw   = (const float*)d_in[1];
    const float* eb   = (const float*)d_in[2];
    const float* wgu  = (const float*)d_in[3];
    const float* wd   = (const float*)d_in[4];
    const float* shgu = (const float*)d_in[5];
    const float* shd  = (const float*)d_in[6];
    float* out = (float*)d_out;

    const int smem1 = (2 * BM * AS_P + 4 * BK * BGP) * 4;   // 88064 B
    const int smem2 = (2 * BM * AS_P + 2 * BK * BSP2) * 4;  // 86016 B
    cudaFuncSetAttribute(k_gemm1, cudaFuncAttributeMaxDynamicSharedMemorySize, smem1);
    cudaFuncSetAttribute(k_gemm2, cudaFuncAttributeMaxDynamicSharedMemorySize, smem2);

    k_prep<<<Tn * Hn / 4 / 256, 256>>>(x);
    k_logits<<<Tn / 8, 256>>>(x, gw, eb);
    k_topk<<<Tn / 8, 256>>>();
    k_scan<<<1, 128>>>();
    k_gemm1<<<dim3(16 * 4, NV), 128, smem1>>>(wgu, shgu);
    k_gemm2<<<dim3(16 * 4, NV), 128, smem2>>>(wd, shd);
    k_combine<<<Tn, 256>>>(out);
}